// round 8
// baseline (speedup 1.0000x reference)
#include <cuda_runtime.h>
#include <cuda_fp16.h>

#define TT  30
#define TD  150
#define DIM 512
#define MAX_ROWS 34836   // WORDS_CNT + 1

// fp16 copy of the embedding table (zero-init .bss, no allocation)
__device__ __half g_w2v_h[(size_t)MAX_ROWS * DIM];

// ---- pass 1: fp32 -> fp16 table conversion ----------------------------------
// Coalesced float4 loads (16B/thread stride), uint2 stores. Grid-stride x8.
__global__ __launch_bounds__(256)
void w2v_convert_kernel(const float4* __restrict__ src, uint2* __restrict__ dst, int n4)
{
    const int stride = gridDim.x * 256;
    int i = blockIdx.x * 256 + threadIdx.x;

    for (; i + 7 * stride < n4; i += 8 * stride) {
        float4 f[8];
        #pragma unroll
        for (int k = 0; k < 8; k++) f[k] = __ldcs(&src[i + k * stride]);
        #pragma unroll
        for (int k = 0; k < 8; k++) {
            __half2 a = __floats2half2_rn(f[k].x, f[k].y);
            __half2 b = __floats2half2_rn(f[k].z, f[k].w);
            uint2 u;
            u.x = *reinterpret_cast<unsigned*>(&a);
            u.y = *reinterpret_cast<unsigned*>(&b);
            dst[i + k * stride] = u;
        }
    }
    for (; i < n4; i += stride) {
        float4 f = __ldcs(&src[i]);
        __half2 a = __floats2half2_rn(f.x, f.y), b = __floats2half2_rn(f.z, f.w);
        uint2 u; u.x = *(unsigned*)&a; u.y = *(unsigned*)&b;
        dst[i] = u;
    }
}

// ---- pass 2: gather + pool -----------------------------------------------------
// Grid = 2*B, 64 threads/CTA. CTAs [0,B) = DESC (long, scheduled first),
// CTAs [B,2B) = TITLE (short). Each thread owns 8 dims end-to-end: one LDG.128
// per token, hmax2 max (exact), fp32 sums. No cross-thread merging.
__global__ __launch_bounds__(64)
void swem_cat_kernel(const void* __restrict__ title_v,
                     const void* __restrict__ desc_v,
                     const void* __restrict__ tlen_v,
                     const void* __restrict__ dlen_v,
                     float* __restrict__ out,
                     int B)
{
    __shared__ int s_off[TD];     // pre-scaled byte offsets (idx * 1024)
    __shared__ int s_len;
    __shared__ int s_is64;

    const int cta  = blockIdx.x;
    const int tid  = threadIdx.x;
    const bool isDesc = (cta < B);
    const int b    = isDesc ? cta : (cta - B);
    const int nTok = isDesc ? TD : TT;

    // dtype detection: int64 vs int32 indices (values < 34836 => high word 0)
    if (tid < 32) {
        unsigned hi  = ((const unsigned*)title_v)[2 * tid + 1];
        unsigned any = __ballot_sync(0xffffffffu, hi != 0u);
        if (tid == 0) s_is64 = (any == 0u) ? 1 : 0;
    }
    __syncthreads();

    const void* idx_v = isDesc ? desc_v : title_v;
    const void* len_v = isDesc ? dlen_v : tlen_v;

    if (s_is64) {
        const long long* ip = (const long long*)idx_v + (long long)b * nTok;
        for (int i = tid; i < nTok; i += 64) s_off[i] = ((int)ip[i]) << 10;
        if (tid == 0) s_len = (int)((const long long*)len_v)[b];
    } else {
        const int* ip = (const int*)idx_v + b * nTok;
        for (int i = tid; i < nTok; i += 64) s_off[i] = ip[i] << 10;
        if (tid == 0) s_len = ((const int*)len_v)[b];
    }
    __syncthreads();

    const int len = s_len;
    const char* hbase = (const char*)g_w2v_h + tid * 16;   // thread's 8-dim slice
    // title writes at +0 (max) / +2*DIM (avg); desc at +DIM / +3*DIM
    float* orow = out + (size_t)b * (4 * DIM) + (isDesc ? DIM : 0) + tid * 8;

    const __half2 NEGH2 = __halves2half2(__ushort_as_half(0xFC00),
                                         __ushort_as_half(0xFC00)); // (-inf,-inf)

    __half2 mx0 = NEGH2, mx1 = NEGH2, mx2 = NEGH2, mx3 = NEGH2;
    float sm0=0.f, sm1=0.f, sm2=0.f, sm3=0.f, sm4=0.f, sm5=0.f, sm6=0.f, sm7=0.f;

    #pragma unroll 8
    for (int t = 0; t < len; t++) {
        const uint4 u = *(const uint4*)(hbase + s_off[t]);
        const __half2 h0 = *(const __half2*)&u.x, h1 = *(const __half2*)&u.y;
        const __half2 h2 = *(const __half2*)&u.z, h3 = *(const __half2*)&u.w;
        mx0 = __hmax2(mx0, h0); mx1 = __hmax2(mx1, h1);
        mx2 = __hmax2(mx2, h2); mx3 = __hmax2(mx3, h3);
        float2 f;
        f = __half22float2(h0); sm0 += f.x; sm1 += f.y;
        f = __half22float2(h1); sm2 += f.x; sm3 += f.y;
        f = __half22float2(h2); sm4 += f.x; sm5 += f.y;
        f = __half22float2(h3); sm6 += f.x; sm7 += f.y;
    }

    float4 mxa, mxb, ava, avb;
    if (len > 0) {
        float2 m0 = __half22float2(mx0), m1 = __half22float2(mx1);
        float2 m2 = __half22float2(mx2), m3 = __half22float2(mx3);
        mxa = make_float4(m0.x, m0.y, m1.x, m1.y);
        mxb = make_float4(m2.x, m2.y, m3.x, m3.y);
        const float inv = 1.0f / (float)len;
        ava = make_float4(sm0 * inv, sm1 * inv, sm2 * inv, sm3 * inv);
        avb = make_float4(sm4 * inv, sm5 * inv, sm6 * inv, sm7 * inv);
    } else {
        mxa = mxb = ava = avb = make_float4(0.f, 0.f, 0.f, 0.f);
    }
    *(float4*)(orow)               = mxa;   // max  part
    *(float4*)(orow + 4)           = mxb;
    *(float4*)(orow + 2 * DIM)     = ava;   // avg  part (+2*DIM from max slot)
    *(float4*)(orow + 2 * DIM + 4) = avb;
}

extern "C" void kernel_launch(void* const* d_in, const int* in_sizes, int n_in,
                              void* d_out, int out_size)
{
    const void* title = d_in[0];
    const void* desc  = d_in[1];
    const void* tlen  = d_in[2];
    const void* dlen  = d_in[3];
    const float* w2v  = (const float*)d_in[n_in - 1];
    float* out        = (float*)d_out;

    const int B = in_sizes[2];                        // t_len has B elements

    long long w2v_elems = in_sizes[n_in - 1];
    long long rows = w2v_elems / DIM;
    if (rows > MAX_ROWS) rows = MAX_ROWS;
    const int n4 = (int)(rows * (DIM / 4));           // float4 chunks

    __half* dsth;
    cudaGetSymbolAddress((void**)&dsth, g_w2v_h);     // address only, no alloc

    w2v_convert_kernel<<<1184, 256>>>((const float4*)w2v, (uint2*)dsth, n4);
    swem_cat_kernel<<<2 * B, 64>>>(title, desc, tlen, dlen, out, B);
}

// round 9
// speedup vs baseline: 1.1904x; 1.1904x over previous
#include <cuda_runtime.h>
#include <cuda_fp16.h>

#define TT  30
#define TD  150
#define DIM 512
#define MAX_ROWS 34836   // WORDS_CNT + 1

// fp16 copy of the embedding table (zero-init .bss, no allocation)
__device__ __half g_w2v_h[(size_t)MAX_ROWS * DIM];

// ---- pass 1: fp32 -> fp16 table conversion ----------------------------------
__global__ __launch_bounds__(256)
void w2v_convert_kernel(const float4* __restrict__ src, uint2* __restrict__ dst, int n4)
{
    const int stride = gridDim.x * 256;
    int i = blockIdx.x * 256 + threadIdx.x;

    for (; i + 7 * stride < n4; i += 8 * stride) {
        float4 f[8];
        #pragma unroll
        for (int k = 0; k < 8; k++) f[k] = __ldcs(&src[i + k * stride]);
        #pragma unroll
        for (int k = 0; k < 8; k++) {
            __half2 a = __floats2half2_rn(f[k].x, f[k].y);
            __half2 b = __floats2half2_rn(f[k].z, f[k].w);
            uint2 u;
            u.x = *reinterpret_cast<unsigned*>(&a);
            u.y = *reinterpret_cast<unsigned*>(&b);
            dst[i + k * stride] = u;
        }
    }
    for (; i < n4; i += stride) {
        float4 f = __ldcs(&src[i]);
        __half2 a = __floats2half2_rn(f.x, f.y), b = __floats2half2_rn(f.z, f.w);
        uint2 u; u.x = *(unsigned*)&a; u.y = *(unsigned*)&b;
        dst[i] = u;
    }
}

// ---- pass 2: gather + pool -----------------------------------------------------
// Fine-grained: 32-thread CTAs, each CTA = (pool, row, dim-half).
//   CTAs [0, 2B)      : DESC  — cta/2 = row, cta&1 = half   (long work first)
//   CTAs [2B, 4B)     : TITLE — (cta-2B)/2 = row, &1 = half
// Thread owns 8 dims (one LDG.128 per token). Max via hmax2 (exact),
// sums via fp16 pair-add then fp32 accumulate. No cross-thread merging.
__global__ __launch_bounds__(32)
void swem_cat_kernel(const void* __restrict__ title_v,
                     const void* __restrict__ desc_v,
                     const void* __restrict__ tlen_v,
                     const void* __restrict__ dlen_v,
                     float* __restrict__ out,
                     int B)
{
    __shared__ int s_off[TD];     // pre-scaled byte offsets (idx * 1024)
    __shared__ int s_len;
    __shared__ int s_is64;

    const int cta = blockIdx.x;
    const int tid = threadIdx.x;
    const bool isDesc = (cta < 2 * B);
    const int local   = isDesc ? cta : (cta - 2 * B);
    const int b       = local >> 1;
    const int half    = local & 1;
    const int nTok    = isDesc ? TD : TT;

    // dtype detection: int64 vs int32 indices (values < 34836 => high word 0)
    {
        unsigned hi  = ((const unsigned*)title_v)[2 * tid + 1];
        unsigned any = __ballot_sync(0xffffffffu, hi != 0u);
        if (tid == 0) s_is64 = (any == 0u) ? 1 : 0;
    }
    __syncthreads();

    const void* idx_v = isDesc ? desc_v : title_v;
    const void* len_v = isDesc ? dlen_v : tlen_v;

    if (s_is64) {
        const long long* ip = (const long long*)idx_v + (long long)b * nTok;
        for (int i = tid; i < nTok; i += 32) s_off[i] = ((int)ip[i]) << 10;
        if (tid == 0) s_len = (int)((const long long*)len_v)[b];
    } else {
        const int* ip = (const int*)idx_v + b * nTok;
        for (int i = tid; i < nTok; i += 32) s_off[i] = ip[i] << 10;
        if (tid == 0) s_len = ((const int*)len_v)[b];
    }
    __syncthreads();

    const int len = s_len;
    // this CTA covers dims [half*256, half*256+256); thread slice = 8 dims
    const char* hbase = (const char*)g_w2v_h + half * 512 + tid * 16;
    float* orow = out + (size_t)b * (4 * DIM) + (isDesc ? DIM : 0)
                      + half * 256 + tid * 8;

    const __half2 NEGH2 = __halves2half2(__ushort_as_half(0xFC00),
                                         __ushort_as_half(0xFC00)); // (-inf,-inf)

    __half2 mx0 = NEGH2, mx1 = NEGH2, mx2 = NEGH2, mx3 = NEGH2;
    float sm0=0.f, sm1=0.f, sm2=0.f, sm3=0.f, sm4=0.f, sm5=0.f, sm6=0.f, sm7=0.f;

    int t = 0;
    #pragma unroll 4
    for (; t + 1 < len; t += 2) {
        const uint4 ua = *(const uint4*)(hbase + s_off[t]);
        const uint4 ub = *(const uint4*)(hbase + s_off[t + 1]);
        const __half2 a0 = *(const __half2*)&ua.x, a1 = *(const __half2*)&ua.y;
        const __half2 a2 = *(const __half2*)&ua.z, a3 = *(const __half2*)&ua.w;
        const __half2 b0 = *(const __half2*)&ub.x, b1 = *(const __half2*)&ub.y;
        const __half2 b2 = *(const __half2*)&ub.z, b3 = *(const __half2*)&ub.w;
        mx0 = __hmax2(mx0, __hmax2(a0, b0));
        mx1 = __hmax2(mx1, __hmax2(a1, b1));
        mx2 = __hmax2(mx2, __hmax2(a2, b2));
        mx3 = __hmax2(mx3, __hmax2(a3, b3));
        // fp16 pair-sum (|a+b| small; err ~5e-4 RMS), then fp32 accumulate
        const __half2 p0 = __hadd2(a0, b0), p1 = __hadd2(a1, b1);
        const __half2 p2 = __hadd2(a2, b2), p3 = __hadd2(a3, b3);
        float2 f;
        f = __half22float2(p0); sm0 += f.x; sm1 += f.y;
        f = __half22float2(p1); sm2 += f.x; sm3 += f.y;
        f = __half22float2(p2); sm4 += f.x; sm5 += f.y;
        f = __half22float2(p3); sm6 += f.x; sm7 += f.y;
    }
    if (t < len) {   // odd tail token
        const uint4 u = *(const uint4*)(hbase + s_off[t]);
        const __half2 h0 = *(const __half2*)&u.x, h1 = *(const __half2*)&u.y;
        const __half2 h2 = *(const __half2*)&u.z, h3 = *(const __half2*)&u.w;
        mx0 = __hmax2(mx0, h0); mx1 = __hmax2(mx1, h1);
        mx2 = __hmax2(mx2, h2); mx3 = __hmax2(mx3, h3);
        float2 f;
        f = __half22float2(h0); sm0 += f.x; sm1 += f.y;
        f = __half22float2(h1); sm2 += f.x; sm3 += f.y;
        f = __half22float2(h2); sm4 += f.x; sm5 += f.y;
        f = __half22float2(h3); sm6 += f.x; sm7 += f.y;
    }

    float4 mxa, mxb, ava, avb;
    if (len > 0) {
        float2 m0 = __half22float2(mx0), m1 = __half22float2(mx1);
        float2 m2 = __half22float2(mx2), m3 = __half22float2(mx3);
        mxa = make_float4(m0.x, m0.y, m1.x, m1.y);
        mxb = make_float4(m2.x, m2.y, m3.x, m3.y);
        const float inv = 1.0f / (float)len;
        ava = make_float4(sm0 * inv, sm1 * inv, sm2 * inv, sm3 * inv);
        avb = make_float4(sm4 * inv, sm5 * inv, sm6 * inv, sm7 * inv);
    } else {
        mxa = mxb = ava = avb = make_float4(0.f, 0.f, 0.f, 0.f);
    }
    *(float4*)(orow)               = mxa;   // max quadrant
    *(float4*)(orow + 4)           = mxb;
    *(float4*)(orow + 2 * DIM)     = ava;   // avg quadrant (+2*DIM from max)
    *(float4*)(orow + 2 * DIM + 4) = avb;
}

extern "C" void kernel_launch(void* const* d_in, const int* in_sizes, int n_in,
                              void* d_out, int out_size)
{
    const void* title = d_in[0];
    const void* desc  = d_in[1];
    const void* tlen  = d_in[2];
    const void* dlen  = d_in[3];
    const float* w2v  = (const float*)d_in[n_in - 1];
    float* out        = (float*)d_out;

    const int B = in_sizes[2];                        // t_len has B elements

    long long w2v_elems = in_sizes[n_in - 1];
    long long rows = w2v_elems / DIM;
    if (rows > MAX_ROWS) rows = MAX_ROWS;
    const int n4 = (int)(rows * (DIM / 4));           // float4 chunks

    __half* dsth;
    cudaGetSymbolAddress((void**)&dsth, g_w2v_h);     // address only, no alloc

    w2v_convert_kernel<<<592, 256>>>((const float4*)w2v, (uint2*)dsth, n4);
    swem_cat_kernel<<<4 * B, 32>>>(title, desc, tlen, dlen, out, B);
}